// round 12
// baseline (speedup 1.0000x reference)
#include <cuda_runtime.h>
#include <cuda_fp16.h>
#include <math.h>
#include <stdint.h>
#include <string.h>

// Problem constants (fixed by reference setup_inputs)
#define BATCH 2
#define SEQ   2048
#define DIM   1024
#define HEADS 16
#define DHEAD 64
#define MROWS (BATCH * SEQ)   // 4096
#define QKV_LD (3 * DIM)      // 3072: packed q|k|v row stride

// -------- device scratch ----------------------------------------------------
__device__ __half g_xh[MROWS * DIM];
__device__ __half g_wall[4 * DIM * DIM];   // rows: Wq*s | Wk | Wv | Wff
__device__ __half g_qkv[MROWS * QKV_LD];   // q|k|v interleaved per row
__device__ __half g_vt[MROWS * DIM];       // V transposed per batch: [b][d][s]
__device__ __half g_attn[MROWS * DIM];

__device__ __forceinline__ uint32_t h2_as_u32(__half2 h) {
    uint32_t u;
    memcpy(&u, &h, 4);
    return u;
}

__device__ __forceinline__ void mma_f16(float c[4], const uint32_t a[4],
                                        const uint32_t b[2]) {
    asm volatile(
        "mma.sync.aligned.m16n8k16.row.col.f32.f16.f16.f32 "
        "{%0,%1,%2,%3}, {%4,%5,%6,%7}, {%8,%9}, {%0,%1,%2,%3};\n"
        : "+f"(c[0]), "+f"(c[1]), "+f"(c[2]), "+f"(c[3])
        : "r"(a[0]), "r"(a[1]), "r"(a[2]), "r"(a[3]),
          "r"(b[0]), "r"(b[1]));
}

#define CP_ASYNC16(dst_u32, src_ptr) \
    asm volatile("cp.async.cg.shared.global [%0], [%1], 16;\n" \
                 :: "r"(dst_u32), "l"(src_ptr) : "memory")
#define CP_COMMIT() asm volatile("cp.async.commit_group;\n" ::: "memory")
#define CP_WAIT0()  asm volatile("cp.async.wait_group 0;\n" ::: "memory")

__device__ __forceinline__ uint32_t smem_u32(const void* p) {
    uint32_t a;
    asm("{ .reg .u64 t; cvta.to.shared.u64 t, %1; cvt.u32.u64 %0, t; }"
        : "=r"(a) : "l"(p));
    return a;
}

// ============================================================================
// Converts
// ============================================================================
__global__ __launch_bounds__(256)
void f32_to_f16(const float* __restrict__ in, __half* __restrict__ out, int n)
{
    const int i = (blockIdx.x * 256 + threadIdx.x) * 4;
    if (i < n) {
        float4 v = *(const float4*)(in + i);
        *(__half2*)(out + i)     = __floats2half2_rn(v.x, v.y);
        *(__half2*)(out + i + 2) = __floats2half2_rn(v.z, v.w);
    }
}

// Pack Wq*qscale | Wk | Wv | Wff into g_wall rows [4096][1024].
__global__ __launch_bounds__(256)
void pack_weights(const float* __restrict__ Wq, const float* __restrict__ Wk,
                  const float* __restrict__ Wv, const float* __restrict__ Wf,
                  __half* __restrict__ out)
{
    const int i = (blockIdx.x * 256 + threadIdx.x) * 4;   // over 4M elems
    const int row = i >> 10;             // /1024
    const int sel = row >> 10;           // /1024 -> 0..3
    const int src = (i & (DIM * DIM - 1));
    const float* W = (sel == 0) ? Wq : (sel == 1) ? Wk : (sel == 2) ? Wv : Wf;
    const float s = (sel == 0) ? 0.03125f : 1.0f;   // 1/32, exact in fp16
    float4 v = *(const float4*)(W + src);
    *(__half2*)(out + i)     = __floats2half2_rn(v.x * s, v.y * s);
    *(__half2*)(out + i + 2) = __floats2half2_rn(v.z * s, v.w * s);
}

// ============================================================================
// FP16 tensor-core GEMM: C[M,N] = A[M,K] @ B[N,K]^T (+bias)
// 128x128x32 tiles, 256 threads = 8 warps (4x2), warp tile 32x64.
// ============================================================================
#define HBM 128
#define HBN 128
#define HBK 32
#define HPU 20
#define HT (128 * HPU)

__global__ __launch_bounds__(256)
void gemm_f16(const __half* __restrict__ A, const __half* __restrict__ B,
              void* __restrict__ Cv, int M, int N, int K,
              const float* __restrict__ bias, int out_half)
{
    __shared__ uint32_t sm[2][2 * HT];

    const int tid  = threadIdx.x;
    const int lane = tid & 31;
    const int warp = tid >> 5;
    const int warp_m = warp >> 1;
    const int warp_n = warp & 1;
    const int g = lane >> 2;
    const int t = lane & 3;
    const int row0 = blockIdx.y * HBM;
    const int col0 = blockIdx.x * HBN;

    const uint32_t sm_u32[2] = { smem_u32(sm[0]), smem_u32(sm[1]) };

    const int c0 = tid, c1 = tid + 256;
    const int ar0 = c0 >> 2, ac0 = c0 & 3;
    const int ar1 = c1 >> 2, ac1 = c1 & 3;

    const __half* Ag = A + (size_t)row0 * K;
    const __half* Bg = B + (size_t)col0 * K;

    {
        CP_ASYNC16(sm_u32[0] + (ar0 * HPU) * 4 + ac0 * 16,
                   (const char*)(Ag + (size_t)ar0 * K) + ac0 * 16);
        CP_ASYNC16(sm_u32[0] + (ar1 * HPU) * 4 + ac1 * 16,
                   (const char*)(Ag + (size_t)ar1 * K) + ac1 * 16);
        CP_ASYNC16(sm_u32[0] + (HT + ar0 * HPU) * 4 + ac0 * 16,
                   (const char*)(Bg + (size_t)ar0 * K) + ac0 * 16);
        CP_ASYNC16(sm_u32[0] + (HT + ar1 * HPU) * 4 + ac1 * 16,
                   (const char*)(Bg + (size_t)ar1 * K) + ac1 * 16);
        CP_COMMIT();
    }

    float acc[2][8][4];
#pragma unroll
    for (int i = 0; i < 2; i++)
#pragma unroll
        for (int j = 0; j < 8; j++)
#pragma unroll
            for (int c = 0; c < 4; c++) acc[i][j][c] = 0.f;

    const int NI = K / HBK;
    for (int it = 0; it < NI; it++) {
        const int cur = it & 1, nxt = cur ^ 1;

        CP_WAIT0();
        __syncthreads();

        if (it + 1 < NI) {
            const int koff = (it + 1) * HBK;
            CP_ASYNC16(sm_u32[nxt] + (ar0 * HPU) * 4 + ac0 * 16,
                       (const char*)(Ag + (size_t)ar0 * K + koff) + ac0 * 16);
            CP_ASYNC16(sm_u32[nxt] + (ar1 * HPU) * 4 + ac1 * 16,
                       (const char*)(Ag + (size_t)ar1 * K + koff) + ac1 * 16);
            CP_ASYNC16(sm_u32[nxt] + (HT + ar0 * HPU) * 4 + ac0 * 16,
                       (const char*)(Bg + (size_t)ar0 * K + koff) + ac0 * 16);
            CP_ASYNC16(sm_u32[nxt] + (HT + ar1 * HPU) * 4 + ac1 * 16,
                       (const char*)(Bg + (size_t)ar1 * K + koff) + ac1 * 16);
            CP_COMMIT();
        }

        const uint32_t* As = sm[cur];
        const uint32_t* Bs = sm[cur] + HT;

#pragma unroll
        for (int ks = 0; ks < 2; ks++) {
            uint32_t afrag[2][4];
#pragma unroll
            for (int tm = 0; tm < 2; tm++) {
                const int r = warp_m * 32 + tm * 16 + g;
                afrag[tm][0] = As[r * HPU + ks * 8 + t];
                afrag[tm][1] = As[(r + 8) * HPU + ks * 8 + t];
                afrag[tm][2] = As[r * HPU + ks * 8 + t + 4];
                afrag[tm][3] = As[(r + 8) * HPU + ks * 8 + t + 4];
            }
            uint32_t bfrag[8][2];
#pragma unroll
            for (int tn = 0; tn < 8; tn++) {
                const int n = warp_n * 64 + tn * 8 + g;
                bfrag[tn][0] = Bs[n * HPU + ks * 8 + t];
                bfrag[tn][1] = Bs[n * HPU + ks * 8 + t + 4];
            }
#pragma unroll
            for (int tm = 0; tm < 2; tm++)
#pragma unroll
                for (int tn = 0; tn < 8; tn++)
                    mma_f16(acc[tm][tn], afrag[tm], bfrag[tn]);
        }
    }

#pragma unroll
    for (int tm = 0; tm < 2; tm++) {
#pragma unroll
        for (int tn = 0; tn < 8; tn++) {
            const int r = row0 + warp_m * 32 + tm * 16 + g;
            const int c = col0 + warp_n * 64 + tn * 8 + 2 * t;
            const float b0 = bias ? bias[c]     : 0.f;
            const float b1 = bias ? bias[c + 1] : 0.f;
            float2 v0, v1;
            v0.x = acc[tm][tn][0] + b0;
            v0.y = acc[tm][tn][1] + b1;
            v1.x = acc[tm][tn][2] + b0;
            v1.y = acc[tm][tn][3] + b1;
            if (out_half) {
                __half* Ch = (__half*)Cv;
                *(__half2*)(Ch + (size_t)r * N + c)       = __floats2half2_rn(v0.x, v0.y);
                *(__half2*)(Ch + (size_t)(r + 8) * N + c) = __floats2half2_rn(v1.x, v1.y);
            } else {
                float* C = (float*)Cv;
                *(float2*)(C + (size_t)r * N + c)       = v0;
                *(float2*)(C + (size_t)(r + 8) * N + c) = v1;
            }
        }
    }
}

// ============================================================================
// Transpose V per (b,h): Vt[b][h*64+d][s] = qkv[b*SEQ+s][2048+h*64+d].
// ============================================================================
__global__ __launch_bounds__(128)
void transpose_v(const __half* __restrict__ Qkv, __half* __restrict__ Vt)
{
    __shared__ __half sm[64][72];
    const int b  = blockIdx.z;
    const int h  = blockIdx.y;
    const int s0 = blockIdx.x * 64;
    const int tid = threadIdx.x;

#pragma unroll
    for (int it = 0; it < 16; it++) {
        const int idx = tid + it * 128;
        const int r  = idx >> 5;
        const int cu = idx & 31;
        *(uint32_t*)&sm[r][cu * 2] =
            *(const uint32_t*)&Qkv[((size_t)(b * SEQ + s0 + r)) * QKV_LD
                                   + 2 * DIM + h * 64 + cu * 2];
    }
    __syncthreads();

#pragma unroll
    for (int it = 0; it < 16; it++) {
        const int idx = tid + it * 128;
        const int d  = idx >> 5;
        const int su = idx & 31;
        __half2 hv;
        hv.x = sm[2 * su][d];
        hv.y = sm[2 * su + 1][d];
        *(__half2*)&Vt[((size_t)(b * DIM + h * 64 + d)) * SEQ + s0 + 2 * su] = hv;
    }
}

// ============================================================================
// FP16 flash attention, 128 q-rows per CTA (256 thr / 8 warps, 16 rows/warp).
// K, V^T double-buffered in smem (shared by all 8 warps -> KV traffic halved
// vs 64-row CTA). Q/K read from packed qkv (row stride QKV_LD).
// ============================================================================
#define PU 36
#define HTILE (64 * PU)
#define FA_SMEM (4 * HTILE * 4)       // 36864 bytes

__global__ __launch_bounds__(256, 2)
void flash_attn_f16(const __half* __restrict__ Qkv, const __half* __restrict__ Vt,
                    __half* __restrict__ O)
{
    extern __shared__ uint32_t usm[];
    uint32_t* Kb[2] = { usm,             usm + HTILE };
    uint32_t* Vb[2] = { usm + 2 * HTILE, usm + 3 * HTILE };

    const int b  = blockIdx.z;
    const int h  = blockIdx.y;
    const int q0 = blockIdx.x * 128;

    const int tid  = threadIdx.x;
    const int lane = tid & 31;
    const int warp = tid >> 5;          // 0..7
    const int g = lane >> 2;
    const int t = lane & 3;
    const int wrow = warp * 16;

    const uint32_t kb_u32[2] = { smem_u32(Kb[0]), smem_u32(Kb[1]) };
    const uint32_t vb_u32[2] = { smem_u32(Vb[0]), smem_u32(Vb[1]) };

    const __half* Qg  = Qkv + h * 64;                                  // +row*QKV_LD
    const __half* Kg  = Qkv + DIM + h * 64 + ((size_t)b * SEQ) * QKV_LD;
    const __half* Vtg = Vt + ((size_t)b * DIM + h * 64) * SEQ;

    // ---- issue K(0), V(0): 512 chunks each, 2 per thread ----
#pragma unroll
    for (int it = 0; it < 2; it++) {
        const int c = tid + it * 256;
        const int row = c >> 3, ch = c & 7;
        CP_ASYNC16(kb_u32[0] + row * PU * 4 + ch * 16,
                   (const char*)(Kg + (size_t)row * QKV_LD) + ch * 16);
    }
#pragma unroll
    for (int it = 0; it < 2; it++) {
        const int c = tid + it * 256;
        const int row = c >> 3, ch = c & 7;
        CP_ASYNC16(vb_u32[0] + row * PU * 4 + ch * 16,
                   (const char*)(Vtg + (size_t)row * SEQ) + ch * 16);
    }
    CP_COMMIT();

    // ---- Q fragments from gmem (packed layout) ----
    uint32_t qf[4][4];
#pragma unroll
    for (int ks = 0; ks < 4; ks++) {
        const size_t rlo = (size_t)(b * SEQ + q0 + wrow + g) * QKV_LD + ks * 16 + 2 * t;
        const size_t rhi = rlo + 8 * QKV_LD;
        qf[ks][0] = *(const uint32_t*)(Qg + rlo);
        qf[ks][1] = *(const uint32_t*)(Qg + rhi);
        qf[ks][2] = *(const uint32_t*)(Qg + rlo + 8);
        qf[ks][3] = *(const uint32_t*)(Qg + rhi + 8);
    }

    float oacc[8][4];
#pragma unroll
    for (int j = 0; j < 8; j++)
#pragma unroll
        for (int c = 0; c < 4; c++) oacc[j][c] = 0.f;
    float m_lo = -INFINITY, m_hi = -INFINITY;
    float l_lo = 0.f, l_hi = 0.f;

    const int NT = SEQ / 64;   // 32
    for (int ti = 0; ti < NT; ti++) {
        const int cur = ti & 1, nxt = cur ^ 1;

        CP_WAIT0();
        __syncthreads();

        if (ti + 1 < NT) {
            const __half* Kg1  = Kg + (size_t)(ti + 1) * 64 * QKV_LD;
            const __half* Vtg1 = Vtg + (size_t)(ti + 1) * 64;
#pragma unroll
            for (int it = 0; it < 2; it++) {
                const int c = tid + it * 256;
                const int row = c >> 3, ch = c & 7;
                CP_ASYNC16(kb_u32[nxt] + row * PU * 4 + ch * 16,
                           (const char*)(Kg1 + (size_t)row * QKV_LD) + ch * 16);
            }
#pragma unroll
            for (int it = 0; it < 2; it++) {
                const int c = tid + it * 256;
                const int row = c >> 3, ch = c & 7;
                CP_ASYNC16(vb_u32[nxt] + row * PU * 4 + ch * 16,
                           (const char*)(Vtg1 + (size_t)row * SEQ) + ch * 16);
            }
            CP_COMMIT();
        }

        const uint32_t* K_s = Kb[cur];
        const uint32_t* V_s = Vb[cur];

        // ---- S = Q @ K^T ----
        float sacc[8][4];
#pragma unroll
        for (int j = 0; j < 8; j++)
#pragma unroll
            for (int c = 0; c < 4; c++) sacc[j][c] = 0.f;

#pragma unroll
        for (int ks = 0; ks < 4; ks++) {
#pragma unroll
            for (int j = 0; j < 8; j++) {
                uint32_t bf[2];
                bf[0] = K_s[(j * 8 + g) * PU + ks * 8 + t];
                bf[1] = K_s[(j * 8 + g) * PU + ks * 8 + t + 4];
                mma_f16(sacc[j], qf[ks], bf);
            }
        }

        // ---- online softmax ----
        float mx_lo = -INFINITY, mx_hi = -INFINITY;
#pragma unroll
        for (int j = 0; j < 8; j++) {
            mx_lo = fmaxf(mx_lo, fmaxf(sacc[j][0], sacc[j][1]));
            mx_hi = fmaxf(mx_hi, fmaxf(sacc[j][2], sacc[j][3]));
        }
        mx_lo = fmaxf(mx_lo, __shfl_xor_sync(0xffffffffu, mx_lo, 1));
        mx_lo = fmaxf(mx_lo, __shfl_xor_sync(0xffffffffu, mx_lo, 2));
        mx_hi = fmaxf(mx_hi, __shfl_xor_sync(0xffffffffu, mx_hi, 1));
        mx_hi = fmaxf(mx_hi, __shfl_xor_sync(0xffffffffu, mx_hi, 2));

        const float mnew_lo = fmaxf(m_lo, mx_lo);
        const float mnew_hi = fmaxf(m_hi, mx_hi);
        const float corr_lo = __expf(m_lo - mnew_lo);
        const float corr_hi = __expf(m_hi - mnew_hi);
        m_lo = mnew_lo; m_hi = mnew_hi;

        uint32_t ph_lo[8], ph_hi[8];
        float sum_lo = 0.f, sum_hi = 0.f;
#pragma unroll
        for (int j = 0; j < 8; j++) {
            const float p0 = __expf(sacc[j][0] - mnew_lo);
            const float p1 = __expf(sacc[j][1] - mnew_lo);
            const float p2 = __expf(sacc[j][2] - mnew_hi);
            const float p3 = __expf(sacc[j][3] - mnew_hi);
            sum_lo += p0 + p1;
            sum_hi += p2 + p3;
            ph_lo[j] = h2_as_u32(__floats2half2_rn(p0, p1));
            ph_hi[j] = h2_as_u32(__floats2half2_rn(p2, p3));
        }
        sum_lo += __shfl_xor_sync(0xffffffffu, sum_lo, 1);
        sum_lo += __shfl_xor_sync(0xffffffffu, sum_lo, 2);
        sum_hi += __shfl_xor_sync(0xffffffffu, sum_hi, 1);
        sum_hi += __shfl_xor_sync(0xffffffffu, sum_hi, 2);
        l_lo = l_lo * corr_lo + sum_lo;
        l_hi = l_hi * corr_hi + sum_hi;

#pragma unroll
        for (int j = 0; j < 8; j++) {
            oacc[j][0] *= corr_lo; oacc[j][1] *= corr_lo;
            oacc[j][2] *= corr_hi; oacc[j][3] *= corr_hi;
        }

        // ---- O += P @ V ----
#pragma unroll
        for (int ks = 0; ks < 4; ks++) {
            uint32_t af[4];
            af[0] = ph_lo[2 * ks];
            af[1] = ph_hi[2 * ks];
            af[2] = ph_lo[2 * ks + 1];
            af[3] = ph_hi[2 * ks + 1];
#pragma unroll
            for (int j = 0; j < 8; j++) {
                uint32_t bf[2];
                bf[0] = V_s[(j * 8 + g) * PU + ks * 8 + t];
                bf[1] = V_s[(j * 8 + g) * PU + ks * 8 + t + 4];
                mma_f16(oacc[j], af, bf);
            }
        }
    }

    // ---- epilogue (fp16 out, compact DIM stride) ----
    __half* Og = O + (size_t)b * SEQ * DIM + h * DHEAD;
    const float inv_lo = 1.f / l_lo;
    const float inv_hi = 1.f / l_hi;
    const int r_lo = q0 + wrow + g;
    const int r_hi = r_lo + 8;
#pragma unroll
    for (int j = 0; j < 8; j++) {
        const int c = j * 8 + 2 * t;
        *(__half2*)(Og + (size_t)r_lo * DIM + c) =
            __floats2half2_rn(oacc[j][0] * inv_lo, oacc[j][1] * inv_lo);
        *(__half2*)(Og + (size_t)r_hi * DIM + c) =
            __floats2half2_rn(oacc[j][2] * inv_hi, oacc[j][3] * inv_hi);
    }
}

// ============================================================================
// kernel_launch
// ============================================================================
extern "C" void kernel_launch(void* const* d_in, const int* in_sizes, int n_in,
                              void* d_out, int out_size)
{
    const float* x   = (const float*)d_in[0];
    const float* Wq  = (const float*)d_in[1];
    const float* Wk  = (const float*)d_in[2];
    const float* Wv  = (const float*)d_in[3];
    const float* Wff = (const float*)d_in[4];
    const float* bff = (const float*)d_in[5];
    float* out = (float*)d_out;

    __half *xh, *wall, *qkv, *vt, *attn;
    cudaGetSymbolAddress((void**)&xh,   g_xh);
    cudaGetSymbolAddress((void**)&wall, g_wall);
    cudaGetSymbolAddress((void**)&qkv,  g_qkv);
    cudaGetSymbolAddress((void**)&vt,   g_vt);
    cudaGetSymbolAddress((void**)&attn, g_attn);

    cudaFuncSetAttribute(flash_attn_f16,
                         cudaFuncAttributeMaxDynamicSharedMemorySize, FA_SMEM);

    // ---- converts (2 launches) ----
    const int nx = MROWS * DIM;        // 4M
    f32_to_f16<<<nx / 1024, 256>>>(x, xh, nx);
    pack_weights<<<(4 * DIM * DIM) / 1024, 256>>>(Wq, Wk, Wv, Wff, wall);

    // ---- fused QKV GEMM: [4096,1024] @ [3072,1024]^T -> qkv ----
    dim3 qkv_grid(QKV_LD / HBN, MROWS / HBM);   // (24, 32)
    gemm_f16<<<qkv_grid, 256>>>(xh, wall, qkv, MROWS, QKV_LD, DIM, nullptr, 1);

    dim3 tr_grid(SEQ / 64, HEADS, BATCH);
    transpose_v<<<tr_grid, 128>>>(qkv, vt);

    dim3 att_grid(SEQ / 128, HEADS, BATCH);     // (16, 16, 2)
    flash_attn_f16<<<att_grid, 256, FA_SMEM>>>(qkv, vt, attn);

    // ---- FF GEMM ----
    dim3 ff_grid(DIM / HBN, MROWS / HBM);       // (8, 32)
    gemm_f16<<<ff_grid, 256>>>(attn, wall + (size_t)3 * DIM * DIM, out,
                               MROWS, DIM, DIM, bff, 0);
}

// round 17
// speedup vs baseline: 1.0765x; 1.0765x over previous
#include <cuda_runtime.h>
#include <cuda_fp16.h>
#include <math.h>
#include <stdint.h>
#include <string.h>

// Problem constants (fixed by reference setup_inputs)
#define BATCH 2
#define SEQ   2048
#define DIM   1024
#define HEADS 16
#define DHEAD 64
#define MROWS (BATCH * SEQ)   // 4096
#define QKV_LD (3 * DIM)      // 3072: packed q|k|v row stride

// -------- device scratch ----------------------------------------------------
__device__ __half g_xh[MROWS * DIM];
__device__ __half g_wall[4 * DIM * DIM];   // rows: Wq*s | Wk | Wv | Wff
__device__ __half g_qkv[MROWS * QKV_LD];   // q|k|v interleaved per row
__device__ __half g_vt[MROWS * DIM];       // V transposed per batch: [b][d][s]
__device__ __half g_attn[MROWS * DIM];

__device__ __forceinline__ uint32_t h2_as_u32(__half2 h) {
    uint32_t u;
    memcpy(&u, &h, 4);
    return u;
}

__device__ __forceinline__ void mma_f16(float c[4], const uint32_t a[4],
                                        const uint32_t b[2]) {
    asm volatile(
        "mma.sync.aligned.m16n8k16.row.col.f32.f16.f16.f32 "
        "{%0,%1,%2,%3}, {%4,%5,%6,%7}, {%8,%9}, {%0,%1,%2,%3};\n"
        : "+f"(c[0]), "+f"(c[1]), "+f"(c[2]), "+f"(c[3])
        : "r"(a[0]), "r"(a[1]), "r"(a[2]), "r"(a[3]),
          "r"(b[0]), "r"(b[1]));
}

#define CP_ASYNC16(dst_u32, src_ptr) \
    asm volatile("cp.async.cg.shared.global [%0], [%1], 16;\n" \
                 :: "r"(dst_u32), "l"(src_ptr) : "memory")
#define CP_COMMIT() asm volatile("cp.async.commit_group;\n" ::: "memory")
#define CP_WAIT0()  asm volatile("cp.async.wait_group 0;\n" ::: "memory")

__device__ __forceinline__ uint32_t smem_u32(const void* p) {
    uint32_t a;
    asm("{ .reg .u64 t; cvta.to.shared.u64 t, %1; cvt.u32.u64 %0, t; }"
        : "=r"(a) : "l"(p));
    return a;
}

// ============================================================================
// Converts
// ============================================================================
__global__ __launch_bounds__(256)
void f32_to_f16(const float* __restrict__ in, __half* __restrict__ out, int n)
{
    const int i = (blockIdx.x * 256 + threadIdx.x) * 4;
    if (i < n) {
        float4 v = *(const float4*)(in + i);
        *(__half2*)(out + i)     = __floats2half2_rn(v.x, v.y);
        *(__half2*)(out + i + 2) = __floats2half2_rn(v.z, v.w);
    }
}

// Pack Wq*qscale | Wk | Wv | Wff into g_wall rows [4096][1024].
__global__ __launch_bounds__(256)
void pack_weights(const float* __restrict__ Wq, const float* __restrict__ Wk,
                  const float* __restrict__ Wv, const float* __restrict__ Wf,
                  __half* __restrict__ out)
{
    const int i = (blockIdx.x * 256 + threadIdx.x) * 4;   // over 4M elems
    const int row = i >> 10;
    const int sel = row >> 10;
    const int src = (i & (DIM * DIM - 1));
    const float* W = (sel == 0) ? Wq : (sel == 1) ? Wk : (sel == 2) ? Wv : Wf;
    const float s = (sel == 0) ? 0.03125f : 1.0f;   // 1/32, exact in fp16
    float4 v = *(const float4*)(W + src);
    *(__half2*)(out + i)     = __floats2half2_rn(v.x * s, v.y * s);
    *(__half2*)(out + i + 2) = __floats2half2_rn(v.z * s, v.w * s);
}

// ============================================================================
// FP16 tensor-core GEMM: C[M,N] = A[M,K] @ B[N,K]^T (+bias)
// ============================================================================
#define HBM 128
#define HBN 128
#define HBK 32
#define HPU 20
#define HT (128 * HPU)

__global__ __launch_bounds__(256)
void gemm_f16(const __half* __restrict__ A, const __half* __restrict__ B,
              void* __restrict__ Cv, int M, int N, int K,
              const float* __restrict__ bias, int out_half)
{
    __shared__ uint32_t sm[2][2 * HT];

    const int tid  = threadIdx.x;
    const int lane = tid & 31;
    const int warp = tid >> 5;
    const int warp_m = warp >> 1;
    const int warp_n = warp & 1;
    const int g = lane >> 2;
    const int t = lane & 3;
    const int row0 = blockIdx.y * HBM;
    const int col0 = blockIdx.x * HBN;

    const uint32_t sm_u32[2] = { smem_u32(sm[0]), smem_u32(sm[1]) };

    const int c0 = tid, c1 = tid + 256;
    const int ar0 = c0 >> 2, ac0 = c0 & 3;
    const int ar1 = c1 >> 2, ac1 = c1 & 3;

    const __half* Ag = A + (size_t)row0 * K;
    const __half* Bg = B + (size_t)col0 * K;

    {
        CP_ASYNC16(sm_u32[0] + (ar0 * HPU) * 4 + ac0 * 16,
                   (const char*)(Ag + (size_t)ar0 * K) + ac0 * 16);
        CP_ASYNC16(sm_u32[0] + (ar1 * HPU) * 4 + ac1 * 16,
                   (const char*)(Ag + (size_t)ar1 * K) + ac1 * 16);
        CP_ASYNC16(sm_u32[0] + (HT + ar0 * HPU) * 4 + ac0 * 16,
                   (const char*)(Bg + (size_t)ar0 * K) + ac0 * 16);
        CP_ASYNC16(sm_u32[0] + (HT + ar1 * HPU) * 4 + ac1 * 16,
                   (const char*)(Bg + (size_t)ar1 * K) + ac1 * 16);
        CP_COMMIT();
    }

    float acc[2][8][4];
#pragma unroll
    for (int i = 0; i < 2; i++)
#pragma unroll
        for (int j = 0; j < 8; j++)
#pragma unroll
            for (int c = 0; c < 4; c++) acc[i][j][c] = 0.f;

    const int NI = K / HBK;
    for (int it = 0; it < NI; it++) {
        const int cur = it & 1, nxt = cur ^ 1;

        CP_WAIT0();
        __syncthreads();

        if (it + 1 < NI) {
            const int koff = (it + 1) * HBK;
            CP_ASYNC16(sm_u32[nxt] + (ar0 * HPU) * 4 + ac0 * 16,
                       (const char*)(Ag + (size_t)ar0 * K + koff) + ac0 * 16);
            CP_ASYNC16(sm_u32[nxt] + (ar1 * HPU) * 4 + ac1 * 16,
                       (const char*)(Ag + (size_t)ar1 * K + koff) + ac1 * 16);
            CP_ASYNC16(sm_u32[nxt] + (HT + ar0 * HPU) * 4 + ac0 * 16,
                       (const char*)(Bg + (size_t)ar0 * K + koff) + ac0 * 16);
            CP_ASYNC16(sm_u32[nxt] + (HT + ar1 * HPU) * 4 + ac1 * 16,
                       (const char*)(Bg + (size_t)ar1 * K + koff) + ac1 * 16);
            CP_COMMIT();
        }

        const uint32_t* As = sm[cur];
        const uint32_t* Bs = sm[cur] + HT;

#pragma unroll
        for (int ks = 0; ks < 2; ks++) {
            uint32_t afrag[2][4];
#pragma unroll
            for (int tm = 0; tm < 2; tm++) {
                const int r = warp_m * 32 + tm * 16 + g;
                afrag[tm][0] = As[r * HPU + ks * 8 + t];
                afrag[tm][1] = As[(r + 8) * HPU + ks * 8 + t];
                afrag[tm][2] = As[r * HPU + ks * 8 + t + 4];
                afrag[tm][3] = As[(r + 8) * HPU + ks * 8 + t + 4];
            }
            uint32_t bfrag[8][2];
#pragma unroll
            for (int tn = 0; tn < 8; tn++) {
                const int n = warp_n * 64 + tn * 8 + g;
                bfrag[tn][0] = Bs[n * HPU + ks * 8 + t];
                bfrag[tn][1] = Bs[n * HPU + ks * 8 + t + 4];
            }
#pragma unroll
            for (int tm = 0; tm < 2; tm++)
#pragma unroll
                for (int tn = 0; tn < 8; tn++)
                    mma_f16(acc[tm][tn], afrag[tm], bfrag[tn]);
        }
    }

#pragma unroll
    for (int tm = 0; tm < 2; tm++) {
#pragma unroll
        for (int tn = 0; tn < 8; tn++) {
            const int r = row0 + warp_m * 32 + tm * 16 + g;
            const int c = col0 + warp_n * 64 + tn * 8 + 2 * t;
            const float b0 = bias ? bias[c]     : 0.f;
            const float b1 = bias ? bias[c + 1] : 0.f;
            float2 v0, v1;
            v0.x = acc[tm][tn][0] + b0;
            v0.y = acc[tm][tn][1] + b1;
            v1.x = acc[tm][tn][2] + b0;
            v1.y = acc[tm][tn][3] + b1;
            if (out_half) {
                __half* Ch = (__half*)Cv;
                *(__half2*)(Ch + (size_t)r * N + c)       = __floats2half2_rn(v0.x, v0.y);
                *(__half2*)(Ch + (size_t)(r + 8) * N + c) = __floats2half2_rn(v1.x, v1.y);
            } else {
                float* C = (float*)Cv;
                *(float2*)(C + (size_t)r * N + c)       = v0;
                *(float2*)(C + (size_t)(r + 8) * N + c) = v1;
            }
        }
    }
}

// ============================================================================
// Transpose V per (b,h): Vt[b][h*64+d][s] = qkv[b*SEQ+s][2048+h*64+d].
// ============================================================================
__global__ __launch_bounds__(128)
void transpose_v(const __half* __restrict__ Qkv, __half* __restrict__ Vt)
{
    __shared__ __half sm[64][72];
    const int b  = blockIdx.z;
    const int h  = blockIdx.y;
    const int s0 = blockIdx.x * 64;
    const int tid = threadIdx.x;

#pragma unroll
    for (int it = 0; it < 16; it++) {
        const int idx = tid + it * 128;
        const int r  = idx >> 5;
        const int cu = idx & 31;
        *(uint32_t*)&sm[r][cu * 2] =
            *(const uint32_t*)&Qkv[((size_t)(b * SEQ + s0 + r)) * QKV_LD
                                   + 2 * DIM + h * 64 + cu * 2];
    }
    __syncthreads();

#pragma unroll
    for (int it = 0; it < 16; it++) {
        const int idx = tid + it * 128;
        const int d  = idx >> 5;
        const int su = idx & 31;
        __half2 hv;
        hv.x = sm[2 * su][d];
        hv.y = sm[2 * su + 1][d];
        *(__half2*)&Vt[((size_t)(b * DIM + h * 64 + d)) * SEQ + s0 + 2 * su] = hv;
    }
}

// ============================================================================
// FP16 flash attention: 4 warps x 32 q-rows = 128 q-rows/CTA, 128 threads.
// Each warp owns TWO 16-row blocks -> every K/V fragment load feeds 2 mma
// (mma:LDS ratio 1:1, double the old 1:2).
// K, V^T double-buffered (one cp.async group outstanding; proven schedule).
// ============================================================================
#define PU 36
#define HTILE (64 * PU)
#define FA_SMEM (4 * HTILE * 4)       // 36864 bytes

__global__ __launch_bounds__(128, 2)
void flash_attn_f16(const __half* __restrict__ Qkv, const __half* __restrict__ Vt,
                    __half* __restrict__ O)
{
    extern __shared__ uint32_t usm[];
    uint32_t* Kb[2] = { usm,             usm + HTILE };
    uint32_t* Vb[2] = { usm + 2 * HTILE, usm + 3 * HTILE };

    const int b  = blockIdx.z;
    const int h  = blockIdx.y;
    const int q0 = blockIdx.x * 128;

    const int tid  = threadIdx.x;
    const int lane = tid & 31;
    const int warp = tid >> 5;          // 0..3
    const int g = lane >> 2;
    const int t = lane & 3;
    const int wrow = warp * 32;

    const uint32_t kb_u32[2] = { smem_u32(Kb[0]), smem_u32(Kb[1]) };
    const uint32_t vb_u32[2] = { smem_u32(Vb[0]), smem_u32(Vb[1]) };

    const __half* Qg  = Qkv + h * 64;
    const __half* Kg  = Qkv + DIM + h * 64 + ((size_t)b * SEQ) * QKV_LD;
    const __half* Vtg = Vt + ((size_t)b * DIM + h * 64) * SEQ;

    // ---- issue K(0), V(0): 512 chunks each, 4 per thread ----
#pragma unroll
    for (int it = 0; it < 4; it++) {
        const int c = tid + it * 128;
        const int row = c >> 3, ch = c & 7;
        CP_ASYNC16(kb_u32[0] + row * PU * 4 + ch * 16,
                   (const char*)(Kg + (size_t)row * QKV_LD) + ch * 16);
    }
#pragma unroll
    for (int it = 0; it < 4; it++) {
        const int c = tid + it * 128;
        const int row = c >> 3, ch = c & 7;
        CP_ASYNC16(vb_u32[0] + row * PU * 4 + ch * 16,
                   (const char*)(Vtg + (size_t)row * SEQ) + ch * 16);
    }
    CP_COMMIT();

    // ---- Q fragments from gmem: 2 row-blocks ----
    uint32_t qf[2][4][4];
#pragma unroll
    for (int blk = 0; blk < 2; blk++) {
#pragma unroll
        for (int ks = 0; ks < 4; ks++) {
            const size_t rlo = (size_t)(b * SEQ + q0 + wrow + blk * 16 + g) * QKV_LD
                               + ks * 16 + 2 * t;
            const size_t rhi = rlo + 8 * QKV_LD;
            qf[blk][ks][0] = *(const uint32_t*)(Qg + rlo);
            qf[blk][ks][1] = *(const uint32_t*)(Qg + rhi);
            qf[blk][ks][2] = *(const uint32_t*)(Qg + rlo + 8);
            qf[blk][ks][3] = *(const uint32_t*)(Qg + rhi + 8);
        }
    }

    float oacc[2][8][4];
#pragma unroll
    for (int blk = 0; blk < 2; blk++)
#pragma unroll
        for (int j = 0; j < 8; j++)
#pragma unroll
            for (int c = 0; c < 4; c++) oacc[blk][j][c] = 0.f;
    float m_lo[2] = { -INFINITY, -INFINITY }, m_hi[2] = { -INFINITY, -INFINITY };
    float l_lo[2] = { 0.f, 0.f }, l_hi[2] = { 0.f, 0.f };

    const int NT = SEQ / 64;   // 32
    for (int ti = 0; ti < NT; ti++) {
        const int cur = ti & 1, nxt = cur ^ 1;

        CP_WAIT0();
        __syncthreads();

        if (ti + 1 < NT) {
            const __half* Kg1  = Kg + (size_t)(ti + 1) * 64 * QKV_LD;
            const __half* Vtg1 = Vtg + (size_t)(ti + 1) * 64;
#pragma unroll
            for (int it = 0; it < 4; it++) {
                const int c = tid + it * 128;
                const int row = c >> 3, ch = c & 7;
                CP_ASYNC16(kb_u32[nxt] + row * PU * 4 + ch * 16,
                           (const char*)(Kg1 + (size_t)row * QKV_LD) + ch * 16);
            }
#pragma unroll
            for (int it = 0; it < 4; it++) {
                const int c = tid + it * 128;
                const int row = c >> 3, ch = c & 7;
                CP_ASYNC16(vb_u32[nxt] + row * PU * 4 + ch * 16,
                           (const char*)(Vtg1 + (size_t)row * SEQ) + ch * 16);
            }
            CP_COMMIT();
        }

        const uint32_t* K_s = Kb[cur];
        const uint32_t* V_s = Vb[cur];

        // ---- S = Q @ K^T (each bf feeds both row-blocks) ----
        float sacc[2][8][4];
#pragma unroll
        for (int blk = 0; blk < 2; blk++)
#pragma unroll
            for (int j = 0; j < 8; j++)
#pragma unroll
                for (int c = 0; c < 4; c++) sacc[blk][j][c] = 0.f;

#pragma unroll
        for (int ks = 0; ks < 4; ks++) {
#pragma unroll
            for (int j = 0; j < 8; j++) {
                uint32_t bf[2];
                bf[0] = K_s[(j * 8 + g) * PU + ks * 8 + t];
                bf[1] = K_s[(j * 8 + g) * PU + ks * 8 + t + 4];
                mma_f16(sacc[0][j], qf[0][ks], bf);
                mma_f16(sacc[1][j], qf[1][ks], bf);
            }
        }

        // ---- online softmax + pack P (both row-blocks) ----
        uint32_t ph_lo[2][8], ph_hi[2][8];
#pragma unroll
        for (int blk = 0; blk < 2; blk++) {
            float mx_lo = -INFINITY, mx_hi = -INFINITY;
#pragma unroll
            for (int j = 0; j < 8; j++) {
                mx_lo = fmaxf(mx_lo, fmaxf(sacc[blk][j][0], sacc[blk][j][1]));
                mx_hi = fmaxf(mx_hi, fmaxf(sacc[blk][j][2], sacc[blk][j][3]));
            }
            mx_lo = fmaxf(mx_lo, __shfl_xor_sync(0xffffffffu, mx_lo, 1));
            mx_lo = fmaxf(mx_lo, __shfl_xor_sync(0xffffffffu, mx_lo, 2));
            mx_hi = fmaxf(mx_hi, __shfl_xor_sync(0xffffffffu, mx_hi, 1));
            mx_hi = fmaxf(mx_hi, __shfl_xor_sync(0xffffffffu, mx_hi, 2));

            const float mnew_lo = fmaxf(m_lo[blk], mx_lo);
            const float mnew_hi = fmaxf(m_hi[blk], mx_hi);
            const float corr_lo = __expf(m_lo[blk] - mnew_lo);
            const float corr_hi = __expf(m_hi[blk] - mnew_hi);
            m_lo[blk] = mnew_lo; m_hi[blk] = mnew_hi;

            float sum_lo = 0.f, sum_hi = 0.f;
#pragma unroll
            for (int j = 0; j < 8; j++) {
                const float p0 = __expf(sacc[blk][j][0] - mnew_lo);
                const float p1 = __expf(sacc[blk][j][1] - mnew_lo);
                const float p2 = __expf(sacc[blk][j][2] - mnew_hi);
                const float p3 = __expf(sacc[blk][j][3] - mnew_hi);
                sum_lo += p0 + p1;
                sum_hi += p2 + p3;
                ph_lo[blk][j] = h2_as_u32(__floats2half2_rn(p0, p1));
                ph_hi[blk][j] = h2_as_u32(__floats2half2_rn(p2, p3));
            }
            sum_lo += __shfl_xor_sync(0xffffffffu, sum_lo, 1);
            sum_lo += __shfl_xor_sync(0xffffffffu, sum_lo, 2);
            sum_hi += __shfl_xor_sync(0xffffffffu, sum_hi, 1);
            sum_hi += __shfl_xor_sync(0xffffffffu, sum_hi, 2);
            l_lo[blk] = l_lo[blk] * corr_lo + sum_lo;
            l_hi[blk] = l_hi[blk] * corr_hi + sum_hi;

#pragma unroll
            for (int j = 0; j < 8; j++) {
                oacc[blk][j][0] *= corr_lo; oacc[blk][j][1] *= corr_lo;
                oacc[blk][j][2] *= corr_hi; oacc[blk][j][3] *= corr_hi;
            }
        }

        // ---- O += P @ V (each bf feeds both row-blocks) ----
#pragma unroll
        for (int ks = 0; ks < 4; ks++) {
            uint32_t af0[4], af1[4];
            af0[0] = ph_lo[0][2 * ks];     af1[0] = ph_lo[1][2 * ks];
            af0[1] = ph_hi[0][2 * ks];     af1[1] = ph_hi[1][2 * ks];
            af0[2] = ph_lo[0][2 * ks + 1]; af1[2] = ph_lo[1][2 * ks + 1];
            af0[3] = ph_hi[0][2 * ks + 1]; af1[3] = ph_hi[1][2 * ks + 1];
#pragma unroll
            for (int j = 0; j < 8; j++) {
                uint32_t bf[2];
                bf[0] = V_s[(j * 8 + g) * PU + ks * 8 + t];
                bf[1] = V_s[(j * 8 + g) * PU + ks * 8 + t + 4];
                mma_f16(oacc[0][j], af0, bf);
                mma_f16(oacc[1][j], af1, bf);
            }
        }
    }

    // ---- epilogue (fp16 out, compact DIM stride) ----
    __half* Og = O + (size_t)b * SEQ * DIM + h * DHEAD;
#pragma unroll
    for (int blk = 0; blk < 2; blk++) {
        const float inv_lo = 1.f / l_lo[blk];
        const float inv_hi = 1.f / l_hi[blk];
        const int r_lo = q0 + wrow + blk * 16 + g;
        const int r_hi = r_lo + 8;
#pragma unroll
        for (int j = 0; j < 8; j++) {
            const int c = j * 8 + 2 * t;
            *(__half2*)(Og + (size_t)r_lo * DIM + c) =
                __floats2half2_rn(oacc[blk][j][0] * inv_lo, oacc[blk][j][1] * inv_lo);
            *(__half2*)(Og + (size_t)r_hi * DIM + c) =
                __floats2half2_rn(oacc[blk][j][2] * inv_hi, oacc[blk][j][3] * inv_hi);
        }
    }
}

// ============================================================================
// kernel_launch
// ============================================================================
extern "C" void kernel_launch(void* const* d_in, const int* in_sizes, int n_in,
                              void* d_out, int out_size)
{
    const float* x   = (const float*)d_in[0];
    const float* Wq  = (const float*)d_in[1];
    const float* Wk  = (const float*)d_in[2];
    const float* Wv  = (const float*)d_in[3];
    const float* Wff = (const float*)d_in[4];
    const float* bff = (const float*)d_in[5];
    float* out = (float*)d_out;

    __half *xh, *wall, *qkv, *vt, *attn;
    cudaGetSymbolAddress((void**)&xh,   g_xh);
    cudaGetSymbolAddress((void**)&wall, g_wall);
    cudaGetSymbolAddress((void**)&qkv,  g_qkv);
    cudaGetSymbolAddress((void**)&vt,   g_vt);
    cudaGetSymbolAddress((void**)&attn, g_attn);

    cudaFuncSetAttribute(flash_attn_f16,
                         cudaFuncAttributeMaxDynamicSharedMemorySize, FA_SMEM);

    // ---- converts (2 launches) ----
    const int nx = MROWS * DIM;
    f32_to_f16<<<nx / 1024, 256>>>(x, xh, nx);
    pack_weights<<<(4 * DIM * DIM) / 1024, 256>>>(Wq, Wk, Wv, Wff, wall);

    // ---- fused QKV GEMM ----
    dim3 qkv_grid(QKV_LD / HBN, MROWS / HBM);   // (24, 32)
    gemm_f16<<<qkv_grid, 256>>>(xh, wall, qkv, MROWS, QKV_LD, DIM, nullptr, 1);

    dim3 tr_grid(SEQ / 64, HEADS, BATCH);
    transpose_v<<<tr_grid, 128>>>(qkv, vt);

    dim3 att_grid(SEQ / 128, HEADS, BATCH);     // (16, 16, 2)
    flash_attn_f16<<<att_grid, 128, FA_SMEM>>>(qkv, vt, attn);

    // ---- FF GEMM ----
    dim3 ff_grid(DIM / HBN, MROWS / HBM);       // (8, 32)
    gemm_f16<<<ff_grid, 256>>>(attn, wall + (size_t)3 * DIM * DIM, out,
                               MROWS, DIM, DIM, bff, 0);
}